// round 10
// baseline (speedup 1.0000x reference)
#include <cuda_runtime.h>

#define N_NODES 100000
#define D_FEAT  128
#define NEG_SLOPE 0.1f

// scratch (allocation-free rule: __device__ globals)
__device__ float g_node_sum[N_NODES];
__device__ float g_r1[N_NODES];

#define A_BLOCKS 592   // 4 blocks/SM * 148 SMs -> exactly one wave
#define A_THREADS 256  // 8 warps/block -> 32 warps/SM

// Kernel A: persistent single-wave. Each warp grid-strides over groups of 8
// nodes; lane l loads float4 #l of each of the 8 rows (8 independent LDG.128
// per iteration, loop iterations overlap). 100000 = 8*12500 -> full groups.
// Also zero-initializes r1. Triggers PDL so kernel B can start prefetching.
__global__ void __launch_bounds__(A_THREADS, 4)
node_sum_kernel(const float* __restrict__ feat) {
    int gwarp = (blockIdx.x * A_THREADS + threadIdx.x) >> 5;
    int lane  = threadIdx.x & 31;
    int nwarps = (A_BLOCKS * A_THREADS) >> 5;
    const float4* f4 = reinterpret_cast<const float4*>(feat);
    const int ngroups = N_NODES / 8;  // 12500

    for (int g = gwarp; g < ngroups; g += nwarps) {
        int node0 = g * 8;
        float4 v[8];
        #pragma unroll
        for (int k = 0; k < 8; k++)
            v[k] = f4[(size_t)(node0 + k) * 32 + lane];

        float s[8];
        #pragma unroll
        for (int k = 0; k < 8; k++)
            s[k] = (v[k].x + v[k].y) + (v[k].z + v[k].w);

        #pragma unroll
        for (int o = 16; o > 0; o >>= 1) {
            #pragma unroll
            for (int k = 0; k < 8; k++)
                s[k] += __shfl_xor_sync(0xFFFFFFFFu, s[k], o);
        }
        if (lane == 0) {
            #pragma unroll
            for (int k = 0; k < 8; k++) {
                g_node_sum[node0 + k] = s[k];
                g_r1[node0 + k] = 0.0f;
            }
        }
    }
    // Allow the PDL-dependent edge kernel to start occupying SMs.
    cudaTriggerProgrammaticLaunchCompletion();
}

// Kernel B: per-edge scatter-add of precomputed node sums (indices int32).
// PDL: front-load the int4 edge indices (independent of kernel A's output),
// then cudaGridDependencySynchronize() to wait for A's writes, then the
// L2-resident gather + REDG atomics. 4 edges/thread (measured optimum).
__global__ void __launch_bounds__(256)
edge_scatter_kernel(const int* __restrict__ src,
                    const int* __restrict__ dst,
                    int n_edges4, int n_edges) {
    int i = blockIdx.x * blockDim.x + threadIdx.x;
    const int4* src4 = reinterpret_cast<const int4*>(src);
    const int4* dst4 = reinterpret_cast<const int4*>(dst);

    int4 s, d;
    bool valid = (i < n_edges4);
    if (valid) {
        s = src4[i];
        d = dst4[i];
    }

    // Wait for kernel A's completion (and memory flush) before touching
    // g_node_sum / g_r1. Index loads above are already in flight.
    cudaGridDependencySynchronize();

    if (valid) {
        atomicAdd(&g_r1[d.x], g_node_sum[s.x]);
        atomicAdd(&g_r1[d.y], g_node_sum[s.y]);
        atomicAdd(&g_r1[d.z], g_node_sum[s.z]);
        atomicAdd(&g_r1[d.w], g_node_sum[s.w]);
    }

    // Scalar tail (n_edges % 4 edges), handled by thread n_edges4.
    if (i == n_edges4) {
        for (int e = n_edges4 * 4; e < n_edges; e++)
            atomicAdd(&g_r1[dst[e]], g_node_sum[src[e]]);
    }
}

// Kernel C: leaky-relu chain + truncate-toward-zero (astype(int32) semantics),
// written as float32 (harness __output__ dtype).
__global__ void epilogue_kernel(float* __restrict__ out) {
    int i = blockIdx.x * blockDim.x + threadIdx.x;
    if (i >= N_NODES) return;
    float r1 = g_r1[i];
    float a1 = (r1 >= 0.0f) ? r1 : NEG_SLOPE * r1;
    float r2 = 16.0f * a1;                       // HIDDEN = 16
    float a2 = (r2 >= 0.0f) ? r2 : NEG_SLOPE * r2;
    float r3 = 10.0f * a2;                       // N_CLASSES = 10
    out[i] = truncf(r3);
}

extern "C" void kernel_launch(void* const* d_in, const int* in_sizes, int n_in,
                              void* d_out, int out_size) {
    const float* feat = (const float*)d_in[0];
    const int*   esrc = (const int*)d_in[1];
    const int*   edst = (const int*)d_in[2];
    int n_edges = in_sizes[1];
    float* out = (float*)d_out;

    // Kernel A: persistent single wave
    node_sum_kernel<<<A_BLOCKS, A_THREADS>>>(feat);

    // Kernel B: launched with programmatic dependent launch so its index
    // prefetch overlaps kernel A's tail.
    {
        int n4 = n_edges / 4;
        int threads = 256;
        int blocks = (n4 + threads) / threads;  // +1 thread slot covers tail

        cudaLaunchConfig_t cfg = {};
        cfg.gridDim = dim3((unsigned)blocks, 1, 1);
        cfg.blockDim = dim3((unsigned)threads, 1, 1);
        cfg.dynamicSmemBytes = 0;
        cfg.stream = 0;
        cudaLaunchAttribute attr[1];
        attr[0].id = cudaLaunchAttributeProgrammaticStreamSerialization;
        attr[0].val.programmaticStreamSerializationAllowed = 1;
        cfg.attrs = attr;
        cfg.numAttrs = 1;
        cudaLaunchKernelEx(&cfg, edge_scatter_kernel, esrc, edst, n4, n_edges);
    }

    // Kernel C
    {
        int threads = 256;
        int blocks = (N_NODES + threads - 1) / threads;
        epilogue_kernel<<<blocks, threads>>>(out);
    }
}